// round 3
// baseline (speedup 1.0000x reference)
#include <cuda_runtime.h>
#include <math.h>

#define Bz 8
#define Tt 2048
#define Dd 1024
#define Pp 512
#define Ss 256
#define Hh 256

typedef unsigned long long ull;

// ---------------- device scratch (static, no allocs) ----------------
__device__ float g_H[Bz * Tt * Hh];          // relu(tokens@w1)   16 MB
__device__ ull   g_keys[Bz * Tt];            // sort keys          128 KB
__device__ float g_sortedTok[Bz * Pp * Dd];  // gathered top-512   16 MB
__device__ float g_summ[Bz * Pp * Ss];       // summaries           4 MB
__device__ float g_poolNew[Bz * Pp * Ss];    // updated pool        4 MB
__device__ float g_priNew[Bz * Pp];          // updated priorities
__device__ int   g_cnt[Bz];                  // updated counts
__device__ float g_q[Bz * Tt * Ss];          // 16 MB
__device__ float g_k[Bz * Pp * Ss];          //  4 MB
__device__ float g_v[Bz * Pp * Dd];          // 16 MB
__device__ float g_attn[Bz * Tt * Pp];       // 32 MB

// ---------------- generic 64x64x16 FP32 tiled GEMM ----------------
// C[M,N] = epi( A[M,K] @ op(B) )   op(B)=B[K,N] (TB=false) or B[N,K]^T (TB=true)
// EPI: 0 none, 1 relu, 2 scale-by-alpha.
// KAHAN: per-k-tile partial + compensated outer sum (high-accuracy path for
// the score MLP, where sort-order bit-stability matters).
template <bool TB, int EPI, bool KAHAN>
__global__ void sgemm(const float* __restrict__ A, const float* __restrict__ Bm,
                      float* __restrict__ C, int M, int N, int K,
                      int lda, int ldb, int ldc,
                      long sA, long sB, long sC, float alpha) {
    A  += (long)blockIdx.z * sA;
    Bm += (long)blockIdx.z * sB;
    C  += (long)blockIdx.z * sC;

    __shared__ __align__(16) float As[16][68];
    __shared__ __align__(16) float Bs[16][68];

    int tid = threadIdx.x;
    int tx = tid & 15, ty = tid >> 4;
    int rowBase = blockIdx.y * 64, colBase = blockIdx.x * 64;

    float acc[4][4] = {};
    float comp[4][4] = {};

    int arow = tid >> 2;          // 0..63
    int acol = (tid & 3) * 4;     // 0,4,8,12
    int bk   = tid >> 4;          // 0..15
    int bc   = (tid & 15) * 4;    // 0..60

    for (int k0 = 0; k0 < K; k0 += 16) {
        float4 a4 = *(const float4*)(A + (long)(rowBase + arow) * lda + k0 + acol);
        As[acol + 0][arow] = a4.x; As[acol + 1][arow] = a4.y;
        As[acol + 2][arow] = a4.z; As[acol + 3][arow] = a4.w;
        if (TB) {
            float4 b4 = *(const float4*)(Bm + (long)(colBase + arow) * ldb + k0 + acol);
            Bs[acol + 0][arow] = b4.x; Bs[acol + 1][arow] = b4.y;
            Bs[acol + 2][arow] = b4.z; Bs[acol + 3][arow] = b4.w;
        } else {
            float4 b4 = *(const float4*)(Bm + (long)(k0 + bk) * ldb + colBase + bc);
            *(float4*)&Bs[bk][bc] = b4;
        }
        __syncthreads();
        if (KAHAN) {
            float tileAcc[4][4] = {};
#pragma unroll
            for (int k = 0; k < 16; k++) {
                float4 av = *(float4*)&As[k][ty * 4];
                float4 bv = *(float4*)&Bs[k][tx * 4];
                float a[4] = {av.x, av.y, av.z, av.w};
                float b[4] = {bv.x, bv.y, bv.z, bv.w};
#pragma unroll
                for (int i = 0; i < 4; i++)
#pragma unroll
                    for (int j = 0; j < 4; j++) tileAcc[i][j] += a[i] * b[j];
            }
            // Kahan-compensated outer accumulation (64 tile partials)
#pragma unroll
            for (int i = 0; i < 4; i++)
#pragma unroll
                for (int j = 0; j < 4; j++) {
                    float y = tileAcc[i][j] - comp[i][j];
                    float t = acc[i][j] + y;
                    comp[i][j] = (t - acc[i][j]) - y;
                    acc[i][j] = t;
                }
        } else {
#pragma unroll
            for (int k = 0; k < 16; k++) {
                float4 av = *(float4*)&As[k][ty * 4];
                float4 bv = *(float4*)&Bs[k][tx * 4];
                float a[4] = {av.x, av.y, av.z, av.w};
                float b[4] = {bv.x, bv.y, bv.z, bv.w};
#pragma unroll
                for (int i = 0; i < 4; i++)
#pragma unroll
                    for (int j = 0; j < 4; j++) acc[i][j] += a[i] * b[j];
            }
        }
        __syncthreads();
    }
#pragma unroll
    for (int i = 0; i < 4; i++) {
        int r = rowBase + ty * 4 + i;
        float4 v;
        v.x = acc[i][0]; v.y = acc[i][1]; v.z = acc[i][2]; v.w = acc[i][3];
        if (EPI == 1) {
            v.x = fmaxf(v.x, 0.f); v.y = fmaxf(v.y, 0.f);
            v.z = fmaxf(v.z, 0.f); v.w = fmaxf(v.w, 0.f);
        }
        if (EPI == 2) { v.x *= alpha; v.y *= alpha; v.z *= alpha; v.w *= alpha; }
        *(float4*)(C + (long)r * ldc + colBase + tx * 4) = v;
    }
}

// ---------------- scores + sort keys (double-precision dot + sigmoid) -------
// score = fp32( 1/(1+exp(-z)) ), z = double dot of fp32 h row with fp32 w2.
// key = (~bits(score)<<32) | t : ascending == descending score, index tiebreak
// (matches stable argsort(-scores)).
__global__ void score_kernel(const float* __restrict__ w2) {
    int tid = threadIdx.x;
    int lane = tid & 31, warp = tid >> 5;
    int row = blockIdx.x * 8 + warp;  // 0..16383
    const float* h = g_H + (long)row * Hh;
    double acc = 0.0;
#pragma unroll
    for (int i = 0; i < 8; i++)
        acc += (double)h[lane + i * 32] * (double)w2[lane + i * 32];
#pragma unroll
    for (int o = 16; o; o >>= 1) acc += __shfl_xor_sync(0xffffffffu, acc, o);
    if (lane == 0) {
        double sc = 1.0 / (1.0 + exp(-acc));
        unsigned bits = __float_as_uint((float)sc);  // sc in (0,1): bit order ok
        g_keys[row] = ((ull)(~bits) << 32) | (unsigned)(row & (Tt - 1));
    }
}

// ---------------- bitonic sort of 2048 keys per batch ----------------
__global__ void sort_kernel() {
    __shared__ ull s[Tt];
    int b = blockIdx.x, tid = threadIdx.x;
    s[tid]        = g_keys[b * Tt + tid];
    s[tid + 1024] = g_keys[b * Tt + tid + 1024];
    __syncthreads();
    for (int k = 2; k <= Tt; k <<= 1) {
        for (int j = k >> 1; j > 0; j >>= 1) {
            for (int i = tid; i < Tt; i += 1024) {
                int ixj = i ^ j;
                if (ixj > i) {
                    bool up = ((i & k) == 0);
                    ull a = s[i], c = s[ixj];
                    if (up ? (a > c) : (a < c)) { s[i] = c; s[ixj] = a; }
                }
            }
            __syncthreads();
        }
    }
    if (tid < Pp) g_keys[b * Tt + tid] = s[tid];
}

// ---------------- gather top-512 token rows ----------------
__global__ void gather_kernel(const float* __restrict__ tokens) {
    int bs = blockIdx.x;            // b*512 + slot
    int b = bs >> 9;
    int slot = bs & (Pp - 1);
    unsigned t = (unsigned)(g_keys[b * Tt + slot] & 0xffffffffULL);
    const float4* src = (const float4*)(tokens + ((size_t)b * Tt + t) * Dd);
    float4* dst = (float4*)(g_sortedTok + (size_t)bs * Dd);
    dst[threadIdx.x] = src[threadIdx.x];
}

// ---------------- sequential pool update (1 block / batch) ----------------
__global__ void update_kernel(const float* __restrict__ pri_in,
                              const int* __restrict__ counts_in) {
    int b = blockIdx.x, tid = threadIdx.x;  // 512 threads
    float mypri = pri_in[b * Pp + tid];     // priorities positive
    int count = counts_in[b];

    __shared__ ull warpmin[16];
    __shared__ ull bestS;

    const float* summB = g_summ + (size_t)b * Pp * Ss;
    float* poolB = g_poolNew + (size_t)b * Pp * Ss;

    for (int s = 0; s < Pp; s++) {
        ull key = g_keys[b * Tt + s];
        float imp = __uint_as_float(~(unsigned)(key >> 32));
        bool has = imp > 0.5f;  // TAU1

        bool add = has && (count < Pp);     // uniform across block
        if (add) {
            int idx = count;
            if (tid == idx) mypri = imp;
            if (tid < Ss) poolB[(size_t)idx * Ss + tid] = summB[(size_t)s * Ss + tid];
            count++;
        }
        bool replace = has && (count >= Pp);  // uniform
        if (replace) {
            ull k2 = (((ull)__float_as_uint(mypri)) << 32) | (unsigned)tid;
#pragma unroll
            for (int o = 16; o; o >>= 1) {
                ull other = __shfl_down_sync(0xffffffffu, k2, o);
                if (other < k2) k2 = other;
            }
            if ((tid & 31) == 0) warpmin[tid >> 5] = k2;
            __syncthreads();
            if (tid == 0) {
                ull m = warpmin[0];
#pragma unroll
                for (int w = 1; w < 16; w++) if (warpmin[w] < m) m = warpmin[w];
                bestS = m;
            }
            __syncthreads();
            ull m = bestS;
            float minp = __uint_as_float((unsigned)(m >> 32));
            int mini = (int)(m & 0xffffffffULL);
            if (imp > minp) {
                if (tid == mini) mypri = imp;
                if (tid < Ss) poolB[(size_t)mini * Ss + tid] = summB[(size_t)s * Ss + tid];
            }
            __syncthreads();
        }
    }
    g_priNew[b * Pp + tid] = mypri;
    if (tid == 0) g_cnt[b] = count;
}

// ---------------- masked softmax over attn rows ----------------
__global__ void softmax_kernel() {
    int row = blockIdx.x;         // b*T + t
    int b = row >> 11;
    int cnt = g_cnt[b];
    float4* rp = (float4*)(g_attn + (size_t)row * Pp);
    int tid = threadIdx.x;        // 128 threads, one float4 each
    float4 v = rp[tid];
    if (cnt == 0) { rp[tid] = make_float4(0.f, 0.f, 0.f, 0.f); return; }

    int p0 = tid * 4;
    float vals[4] = {v.x, v.y, v.z, v.w};
    float m = -INFINITY;
#pragma unroll
    for (int e = 0; e < 4; e++) if (p0 + e < cnt) m = fmaxf(m, vals[e]);

    __shared__ float smax[4], ssum[4];
    int lane = tid & 31, warp = tid >> 5;
#pragma unroll
    for (int o = 16; o; o >>= 1) m = fmaxf(m, __shfl_xor_sync(0xffffffffu, m, o));
    if (lane == 0) smax[warp] = m;
    __syncthreads();
    m = fmaxf(fmaxf(smax[0], smax[1]), fmaxf(smax[2], smax[3]));

    float se = 0.f;
#pragma unroll
    for (int e = 0; e < 4; e++) {
        vals[e] = (p0 + e < cnt) ? expf(vals[e] - m) : 0.f;
        se += vals[e];
    }
#pragma unroll
    for (int o = 16; o; o >>= 1) se += __shfl_xor_sync(0xffffffffu, se, o);
    if (lane == 0) ssum[warp] = se;
    __syncthreads();
    se = ssum[0] + ssum[1] + ssum[2] + ssum[3];

    float inv = 1.f / se;
    rp[tid] = make_float4(vals[0] * inv, vals[1] * inv, vals[2] * inv, vals[3] * inv);
}

__global__ void write_counts(float* dst) {
    if (threadIdx.x < Bz) dst[threadIdx.x] = (float)g_cnt[threadIdx.x];
}

// ---------------- launch ----------------
extern "C" void kernel_launch(void* const* d_in, const int* in_sizes, int n_in,
                              void* d_out, int out_size) {
    const float* tokens = (const float*)d_in[0];
    const float* pool   = (const float*)d_in[1];
    const float* pri    = (const float*)d_in[2];
    const int*   counts = (const int*)d_in[3];
    const float* w1     = (const float*)d_in[4];
    const float* w2     = (const float*)d_in[5];
    const float* w_sum  = (const float*)d_in[6];
    const float* wq     = (const float*)d_in[7];
    const float* wk     = (const float*)d_in[8];
    const float* wv     = (const float*)d_in[9];
    float* out = (float*)d_out;

    float *pH, *pST, *pSm, *pPool, *pPri, *pQ, *pK, *pV, *pAt;
    cudaGetSymbolAddress((void**)&pH, g_H);
    cudaGetSymbolAddress((void**)&pST, g_sortedTok);
    cudaGetSymbolAddress((void**)&pSm, g_summ);
    cudaGetSymbolAddress((void**)&pPool, g_poolNew);
    cudaGetSymbolAddress((void**)&pPri, g_priNew);
    cudaGetSymbolAddress((void**)&pQ, g_q);
    cudaGetSymbolAddress((void**)&pK, g_k);
    cudaGetSymbolAddress((void**)&pV, g_v);
    cudaGetSymbolAddress((void**)&pAt, g_attn);

    dim3 blk(256);

    // 1) H = relu(tokens @ w1)  — high-accuracy (Kahan) path feeding the sort
    sgemm<false, 1, true><<<dim3(Hh / 64, (Bz * Tt) / 64, 1), blk>>>(
        tokens, w1, pH, Bz * Tt, Hh, Dd, Dd, Hh, Hh, 0L, 0L, 0L, 1.f);
    // 2) scores + keys (double dot + double sigmoid, rounded once to fp32)
    score_kernel<<<(Bz * Tt) / 8, 256>>>(w2);
    // 3) per-batch stable descending sort
    sort_kernel<<<Bz, 1024>>>();
    // 4) gather top-512 token rows
    gather_kernel<<<Bz * Pp, 256>>>(tokens);
    // 5) summaries = sortedTok @ w_sum
    sgemm<false, 0, false><<<dim3(Ss / 64, (Bz * Pp) / 64, 1), blk>>>(
        pST, w_sum, pSm, Bz * Pp, Ss, Dd, Dd, Ss, Ss, 0L, 0L, 0L, 1.f);
    // 6) pool copy (inputs stay pristine for graph replays)
    cudaMemcpyAsync(pPool, pool, sizeof(float) * Bz * Pp * Ss,
                    cudaMemcpyDeviceToDevice);
    // 7) sequential priority-pool update
    update_kernel<<<Bz, Pp>>>(pri, counts);
    // 8) q = tokens @ wq
    sgemm<false, 0, false><<<dim3(Ss / 64, (Bz * Tt) / 64, 1), blk>>>(
        tokens, wq, pQ, Bz * Tt, Ss, Dd, Dd, Ss, Ss, 0L, 0L, 0L, 1.f);
    // 9) k = pool_new @ wk
    sgemm<false, 0, false><<<dim3(Ss / 64, (Bz * Pp) / 64, 1), blk>>>(
        pPool, wk, pK, Bz * Pp, Ss, Ss, Ss, Ss, Ss, 0L, 0L, 0L, 1.f);
    // 10) v = pool_new @ wv
    sgemm<false, 0, false><<<dim3(Dd / 64, (Bz * Pp) / 64, 1), blk>>>(
        pPool, wv, pV, Bz * Pp, Dd, Ss, Ss, Dd, Dd, 0L, 0L, 0L, 1.f);
    // 11) attn = (q @ k^T) / 16   batched NT
    sgemm<true, 2, false><<<dim3(Pp / 64, Tt / 64, Bz), blk>>>(
        pQ, pK, pAt, Tt, Pp, Ss, Ss, Ss, Pp,
        (long)Tt * Ss, (long)Pp * Ss, (long)Tt * Pp, 0.0625f);
    // 12) masked softmax
    softmax_kernel<<<Bz * Tt, 128>>>();
    // 13) retrieved = attn @ v   batched NN, straight into out
    sgemm<false, 0, false><<<dim3(Dd / 64, Tt / 64, Bz), blk>>>(
        pAt, pV, out, Tt, Dd, Pp, Pp, Dd, Dd,
        (long)Tt * Pp, (long)Pp * Dd, (long)Tt * Dd, 1.f);

    // tail outputs (pool, priorities, counts) if the output buffer expects them
    long full = (long)Bz * Tt * Dd + (long)Bz * Pp * Ss + Bz * Pp + Bz;
    if ((long)out_size >= full) {
        float* out_pool = out + (size_t)Bz * Tt * Dd;
        float* out_pri  = out_pool + (size_t)Bz * Pp * Ss;
        float* out_cnt  = out_pri + (size_t)Bz * Pp;
        cudaMemcpyAsync(out_pool, pPool, sizeof(float) * Bz * Pp * Ss,
                        cudaMemcpyDeviceToDevice);
        cudaMemcpyAsync(out_pri, pPri, sizeof(float) * Bz * Pp,
                        cudaMemcpyDeviceToDevice);
        write_counts<<<1, 32>>>(out_cnt);
    }
}

// round 4
// speedup vs baseline: 1.0239x; 1.0239x over previous
#include <cuda_runtime.h>
#include <math.h>

#define Bz 8
#define Tt 2048
#define Dd 1024
#define Pp 512
#define Ss 256
#define Hh 256

typedef unsigned long long ull;

// ---------------- device scratch (static, no allocs) ----------------
__device__ float g_H[Bz * Tt * Hh];          // relu(tokens@w1)   16 MB
__device__ ull   g_keys[Bz * Tt];            // sort keys          128 KB
__device__ float g_sortedTok[Bz * Pp * Dd];  // gathered top-512   16 MB
__device__ float g_summ[Bz * Pp * Ss];       // summaries           4 MB
__device__ float g_poolNew[Bz * Pp * Ss];    // updated pool        4 MB
__device__ float g_priNew[Bz * Pp];          // updated priorities
__device__ int   g_cnt[Bz];                  // updated counts
__device__ float g_q[Bz * Tt * Ss];          // 16 MB
__device__ float g_k[Bz * Pp * Ss];          //  4 MB
__device__ float g_v[Bz * Pp * Dd];          // 16 MB
__device__ float g_attn[Bz * Tt * Pp];       // 32 MB

// ---------------- generic 64x64x16 FP32 tiled GEMM ----------------
// C[M,N] = epi( A[M,K] @ op(B) )   op(B)=B[K,N] (TB=false) or B[N,K]^T (TB=true)
// EPI: 0 none, 1 relu, 2 scale-by-alpha.
// KAHAN: per-k-tile partial + compensated outer sum (high-accuracy path for
// the score MLP, where sort-order bit-stability matters).
template <bool TB, int EPI, bool KAHAN>
__global__ void sgemm(const float* __restrict__ A, const float* __restrict__ Bm,
                      float* __restrict__ C, int M, int N, int K,
                      int lda, int ldb, int ldc,
                      long sA, long sB, long sC, float alpha) {
    A  += (long)blockIdx.z * sA;
    Bm += (long)blockIdx.z * sB;
    C  += (long)blockIdx.z * sC;

    __shared__ __align__(16) float As[16][68];
    __shared__ __align__(16) float Bs[16][68];

    int tid = threadIdx.x;
    int tx = tid & 15, ty = tid >> 4;
    int rowBase = blockIdx.y * 64, colBase = blockIdx.x * 64;

    float acc[4][4] = {};
    float comp[4][4] = {};

    int arow = tid >> 2;          // 0..63
    int acol = (tid & 3) * 4;     // 0,4,8,12
    int bk   = tid >> 4;          // 0..15
    int bc   = (tid & 15) * 4;    // 0..60

    for (int k0 = 0; k0 < K; k0 += 16) {
        float4 a4 = *(const float4*)(A + (long)(rowBase + arow) * lda + k0 + acol);
        As[acol + 0][arow] = a4.x; As[acol + 1][arow] = a4.y;
        As[acol + 2][arow] = a4.z; As[acol + 3][arow] = a4.w;
        if (TB) {
            float4 b4 = *(const float4*)(Bm + (long)(colBase + arow) * ldb + k0 + acol);
            Bs[acol + 0][arow] = b4.x; Bs[acol + 1][arow] = b4.y;
            Bs[acol + 2][arow] = b4.z; Bs[acol + 3][arow] = b4.w;
        } else {
            float4 b4 = *(const float4*)(Bm + (long)(k0 + bk) * ldb + colBase + bc);
            *(float4*)&Bs[bk][bc] = b4;
        }
        __syncthreads();
        if (KAHAN) {
            float tileAcc[4][4] = {};
#pragma unroll
            for (int k = 0; k < 16; k++) {
                float4 av = *(float4*)&As[k][ty * 4];
                float4 bv = *(float4*)&Bs[k][tx * 4];
                float a[4] = {av.x, av.y, av.z, av.w};
                float b[4] = {bv.x, bv.y, bv.z, bv.w};
#pragma unroll
                for (int i = 0; i < 4; i++)
#pragma unroll
                    for (int j = 0; j < 4; j++) tileAcc[i][j] += a[i] * b[j];
            }
            // Kahan-compensated outer accumulation (64 tile partials)
#pragma unroll
            for (int i = 0; i < 4; i++)
#pragma unroll
                for (int j = 0; j < 4; j++) {
                    float y = tileAcc[i][j] - comp[i][j];
                    float t = acc[i][j] + y;
                    comp[i][j] = (t - acc[i][j]) - y;
                    acc[i][j] = t;
                }
        } else {
#pragma unroll
            for (int k = 0; k < 16; k++) {
                float4 av = *(float4*)&As[k][ty * 4];
                float4 bv = *(float4*)&Bs[k][tx * 4];
                float a[4] = {av.x, av.y, av.z, av.w};
                float b[4] = {bv.x, bv.y, bv.z, bv.w};
#pragma unroll
                for (int i = 0; i < 4; i++)
#pragma unroll
                    for (int j = 0; j < 4; j++) acc[i][j] += a[i] * b[j];
            }
        }
        __syncthreads();
    }
#pragma unroll
    for (int i = 0; i < 4; i++) {
        int r = rowBase + ty * 4 + i;
        float4 v;
        v.x = acc[i][0]; v.y = acc[i][1]; v.z = acc[i][2]; v.w = acc[i][3];
        if (EPI == 1) {
            v.x = fmaxf(v.x, 0.f); v.y = fmaxf(v.y, 0.f);
            v.z = fmaxf(v.z, 0.f); v.w = fmaxf(v.w, 0.f);
        }
        if (EPI == 2) { v.x *= alpha; v.y *= alpha; v.z *= alpha; v.w *= alpha; }
        *(float4*)(C + (long)r * ldc + colBase + tx * 4) = v;
    }
}

// ---------------- scores + sort keys (double-precision dot + sigmoid) -------
// score = fp32( 1/(1+exp(-z)) ), z = double dot of fp32 h row with fp32 w2.
// key = (~bits(score)<<32) | t : ascending == descending score, index tiebreak
// (matches stable argsort(-scores)).
__global__ void score_kernel(const float* __restrict__ w2) {
    int tid = threadIdx.x;
    int lane = tid & 31, warp = tid >> 5;
    int row = blockIdx.x * 8 + warp;  // 0..16383
    const float* h = g_H + (long)row * Hh;
    double acc = 0.0;
#pragma unroll
    for (int i = 0; i < 8; i++)
        acc += (double)h[lane + i * 32] * (double)w2[lane + i * 32];
#pragma unroll
    for (int o = 16; o; o >>= 1) acc += __shfl_xor_sync(0xffffffffu, acc, o);
    if (lane == 0) {
        double sc = 1.0 / (1.0 + exp(-acc));
        unsigned bits = __float_as_uint((float)sc);  // sc in (0,1): bit order ok
        g_keys[row] = ((ull)(~bits) << 32) | (unsigned)(row & (Tt - 1));
    }
}

// ---------------- bitonic sort of 2048 keys per batch ----------------
__global__ void sort_kernel() {
    __shared__ ull s[Tt];
    int b = blockIdx.x, tid = threadIdx.x;
    s[tid]        = g_keys[b * Tt + tid];
    s[tid + 1024] = g_keys[b * Tt + tid + 1024];
    __syncthreads();
    for (int k = 2; k <= Tt; k <<= 1) {
        for (int j = k >> 1; j > 0; j >>= 1) {
            for (int i = tid; i < Tt; i += 1024) {
                int ixj = i ^ j;
                if (ixj > i) {
                    bool up = ((i & k) == 0);
                    ull a = s[i], c = s[ixj];
                    if (up ? (a > c) : (a < c)) { s[i] = c; s[ixj] = a; }
                }
            }
            __syncthreads();
        }
    }
    if (tid < Pp) g_keys[b * Tt + tid] = s[tid];
}

// ---------------- gather top-512 token rows ----------------
__global__ void gather_kernel(const float* __restrict__ tokens) {
    int bs = blockIdx.x;            // b*512 + slot
    int b = bs >> 9;
    int slot = bs & (Pp - 1);
    unsigned t = (unsigned)(g_keys[b * Tt + slot] & 0xffffffffULL);
    const float4* src = (const float4*)(tokens + ((size_t)b * Tt + t) * Dd);
    float4* dst = (float4*)(g_sortedTok + (size_t)bs * Dd);
    dst[threadIdx.x] = src[threadIdx.x];
}

// ---------------- sequential pool update (1 block / batch) ----------------
__global__ void update_kernel(const float* __restrict__ pri_in,
                              const int* __restrict__ counts_in) {
    int b = blockIdx.x, tid = threadIdx.x;  // 512 threads
    float mypri = pri_in[b * Pp + tid];     // priorities positive
    int count = counts_in[b];

    __shared__ ull warpmin[16];
    __shared__ ull bestS;

    const float* summB = g_summ + (size_t)b * Pp * Ss;
    float* poolB = g_poolNew + (size_t)b * Pp * Ss;

    for (int s = 0; s < Pp; s++) {
        ull key = g_keys[b * Tt + s];
        float imp = __uint_as_float(~(unsigned)(key >> 32));
        bool has = imp > 0.5f;  // TAU1

        bool add = has && (count < Pp);     // uniform across block
        if (add) {
            int idx = count;
            if (tid == idx) mypri = imp;
            if (tid < Ss) poolB[(size_t)idx * Ss + tid] = summB[(size_t)s * Ss + tid];
            count++;
        }
        bool replace = has && (count >= Pp);  // uniform
        if (replace) {
            ull k2 = (((ull)__float_as_uint(mypri)) << 32) | (unsigned)tid;
#pragma unroll
            for (int o = 16; o; o >>= 1) {
                ull other = __shfl_down_sync(0xffffffffu, k2, o);
                if (other < k2) k2 = other;
            }
            if ((tid & 31) == 0) warpmin[tid >> 5] = k2;
            __syncthreads();
            if (tid == 0) {
                ull m = warpmin[0];
#pragma unroll
                for (int w = 1; w < 16; w++) if (warpmin[w] < m) m = warpmin[w];
                bestS = m;
            }
            __syncthreads();
            ull m = bestS;
            float minp = __uint_as_float((unsigned)(m >> 32));
            int mini = (int)(m & 0xffffffffULL);
            if (imp > minp) {
                if (tid == mini) mypri = imp;
                if (tid < Ss) poolB[(size_t)mini * Ss + tid] = summB[(size_t)s * Ss + tid];
            }
            __syncthreads();
        }
    }
    g_priNew[b * Pp + tid] = mypri;
    if (tid == 0) g_cnt[b] = count;
}

// ---------------- masked softmax over attn rows ----------------
__global__ void softmax_kernel() {
    int row = blockIdx.x;         // b*T + t
    int b = row >> 11;
    int cnt = g_cnt[b];
    float4* rp = (float4*)(g_attn + (size_t)row * Pp);
    int tid = threadIdx.x;        // 128 threads, one float4 each
    float4 v = rp[tid];
    if (cnt == 0) { rp[tid] = make_float4(0.f, 0.f, 0.f, 0.f); return; }

    int p0 = tid * 4;
    float vals[4] = {v.x, v.y, v.z, v.w};
    float m = -INFINITY;
#pragma unroll
    for (int e = 0; e < 4; e++) if (p0 + e < cnt) m = fmaxf(m, vals[e]);

    __shared__ float smax[4], ssum[4];
    int lane = tid & 31, warp = tid >> 5;
#pragma unroll
    for (int o = 16; o; o >>= 1) m = fmaxf(m, __shfl_xor_sync(0xffffffffu, m, o));
    if (lane == 0) smax[warp] = m;
    __syncthreads();
    m = fmaxf(fmaxf(smax[0], smax[1]), fmaxf(smax[2], smax[3]));

    float se = 0.f;
#pragma unroll
    for (int e = 0; e < 4; e++) {
        vals[e] = (p0 + e < cnt) ? expf(vals[e] - m) : 0.f;
        se += vals[e];
    }
#pragma unroll
    for (int o = 16; o; o >>= 1) se += __shfl_xor_sync(0xffffffffu, se, o);
    if (lane == 0) ssum[warp] = se;
    __syncthreads();
    se = ssum[0] + ssum[1] + ssum[2] + ssum[3];

    float inv = 1.f / se;
    rp[tid] = make_float4(vals[0] * inv, vals[1] * inv, vals[2] * inv, vals[3] * inv);
}

__global__ void write_counts(float* dst) {
    if (threadIdx.x < Bz) dst[threadIdx.x] = (float)g_cnt[threadIdx.x];
}

// ---------------- launch ----------------
extern "C" void kernel_launch(void* const* d_in, const int* in_sizes, int n_in,
                              void* d_out, int out_size) {
    const float* tokens = (const float*)d_in[0];
    const float* pool   = (const float*)d_in[1];
    const float* pri    = (const float*)d_in[2];
    const int*   counts = (const int*)d_in[3];
    const float* w1     = (const float*)d_in[4];
    const float* w2     = (const float*)d_in[5];
    const float* w_sum  = (const float*)d_in[6];
    const float* wq     = (const float*)d_in[7];
    const float* wk     = (const float*)d_in[8];
    const float* wv     = (const float*)d_in[9];
    float* out = (float*)d_out;

    float *pH, *pST, *pSm, *pPool, *pPri, *pQ, *pK, *pV, *pAt;
    cudaGetSymbolAddress((void**)&pH, g_H);
    cudaGetSymbolAddress((void**)&pST, g_sortedTok);
    cudaGetSymbolAddress((void**)&pSm, g_summ);
    cudaGetSymbolAddress((void**)&pPool, g_poolNew);
    cudaGetSymbolAddress((void**)&pPri, g_priNew);
    cudaGetSymbolAddress((void**)&pQ, g_q);
    cudaGetSymbolAddress((void**)&pK, g_k);
    cudaGetSymbolAddress((void**)&pV, g_v);
    cudaGetSymbolAddress((void**)&pAt, g_attn);

    dim3 blk(256);

    // 1) H = relu(tokens @ w1)  — high-accuracy (Kahan) path feeding the sort
    sgemm<false, 1, true><<<dim3(Hh / 64, (Bz * Tt) / 64, 1), blk>>>(
        tokens, w1, pH, Bz * Tt, Hh, Dd, Dd, Hh, Hh, 0L, 0L, 0L, 1.f);
    // 2) scores + keys (double dot + double sigmoid, rounded once to fp32)
    score_kernel<<<(Bz * Tt) / 8, 256>>>(w2);
    // 3) per-batch stable descending sort
    sort_kernel<<<Bz, 1024>>>();
    // 4) gather top-512 token rows
    gather_kernel<<<Bz * Pp, 256>>>(tokens);
    // 5) summaries = sortedTok @ w_sum
    sgemm<false, 0, false><<<dim3(Ss / 64, (Bz * Pp) / 64, 1), blk>>>(
        pST, w_sum, pSm, Bz * Pp, Ss, Dd, Dd, Ss, Ss, 0L, 0L, 0L, 1.f);
    // 6) pool copy (inputs stay pristine for graph replays)
    cudaMemcpyAsync(pPool, pool, sizeof(float) * Bz * Pp * Ss,
                    cudaMemcpyDeviceToDevice);
    // 7) sequential priority-pool update
    update_kernel<<<Bz, Pp>>>(pri, counts);
    // 8) q = tokens @ wq
    sgemm<false, 0, false><<<dim3(Ss / 64, (Bz * Tt) / 64, 1), blk>>>(
        tokens, wq, pQ, Bz * Tt, Ss, Dd, Dd, Ss, Ss, 0L, 0L, 0L, 1.f);
    // 9) k = pool_new @ wk
    sgemm<false, 0, false><<<dim3(Ss / 64, (Bz * Pp) / 64, 1), blk>>>(
        pPool, wk, pK, Bz * Pp, Ss, Ss, Ss, Ss, Ss, 0L, 0L, 0L, 1.f);
    // 10) v = pool_new @ wv
    sgemm<false, 0, false><<<dim3(Dd / 64, (Bz * Pp) / 64, 1), blk>>>(
        pPool, wv, pV, Bz * Pp, Dd, Ss, Ss, Dd, Dd, 0L, 0L, 0L, 1.f);
    // 11) attn = (q @ k^T) / 16   batched NT
    sgemm<true, 2, false><<<dim3(Pp / 64, Tt / 64, Bz), blk>>>(
        pQ, pK, pAt, Tt, Pp, Ss, Ss, Ss, Pp,
        (long)Tt * Ss, (long)Pp * Ss, (long)Tt * Pp, 0.0625f);
    // 12) masked softmax
    softmax_kernel<<<Bz * Tt, 128>>>();
    // 13) retrieved = attn @ v   batched NN, straight into out
    sgemm<false, 0, false><<<dim3(Dd / 64, Tt / 64, Bz), blk>>>(
        pAt, pV, out, Tt, Dd, Pp, Pp, Dd, Dd,
        (long)Tt * Pp, (long)Pp * Dd, (long)Tt * Dd, 1.f);

    // tail outputs (pool, priorities, counts) if the output buffer expects them
    long full = (long)Bz * Tt * Dd + (long)Bz * Pp * Ss + Bz * Pp + Bz;
    if ((long)out_size >= full) {
        float* out_pool = out + (size_t)Bz * Tt * Dd;
        float* out_pri  = out_pool + (size_t)Bz * Pp * Ss;
        float* out_cnt  = out_pri + (size_t)Bz * Pp;
        cudaMemcpyAsync(out_pool, pPool, sizeof(float) * Bz * Pp * Ss,
                        cudaMemcpyDeviceToDevice);
        cudaMemcpyAsync(out_pri, pPri, sizeof(float) * Bz * Pp,
                        cudaMemcpyDeviceToDevice);
        write_counts<<<1, 32>>>(out_cnt);
    }
}